// round 1
// baseline (speedup 1.0000x reference)
#include <cuda_runtime.h>
#include <cuda_bf16.h>

// BSplineBasis: uniform-knot cubic B-spline closed form.
// x: (4096, 4096) f32, coefficients: (4096, 8) f32, grid: (12,) f32 uniform.
// out[b,s] = sum_{m=0..3} B_m(u) * coeff[s, i-3+m],  i = floor((x-g0)/h), u frac.

#define S_TOTAL 4096
#define B_TOTAL 4096
#define TILE_S  256
#define THREADS 256
#define GRID_Y  64
#define ROWS_PER_BLOCK (B_TOTAL / GRID_Y)   // 64

__global__ __launch_bounds__(THREADS)
void bspline_kernel(const float* __restrict__ x,
                    const float* __restrict__ coeff,
                    const float* __restrict__ grid,
                    float* __restrict__ out)
{
    // Coefficient stage: row stride 9 (coprime with 32 banks) -> conflict-free
    // dynamic LDS even though the 4-float window offset is data-dependent.
    __shared__ float sc[TILE_S * 9];

    const int t  = threadIdx.x;
    const int s  = blockIdx.x * TILE_S + t;

    // Stage this thread's 8 coefficients (32B aligned -> two float4 loads).
    const float4* crow = reinterpret_cast<const float4*>(coeff + (size_t)s * 8);
    float4 ca = crow[0];
    float4 cb4 = crow[1];
    float* dst = &sc[t * 9];
    dst[0] = ca.x;  dst[1] = ca.y;  dst[2] = ca.z;  dst[3] = ca.w;
    dst[4] = cb4.x; dst[5] = cb4.y; dst[6] = cb4.z; dst[7] = cb4.w;
    __syncthreads();

    const float g0   = __ldg(&grid[0]);
    const float h    = __ldg(&grid[1]) - g0;
    const float invh = 1.0f / h;

    const int b0 = blockIdx.y * ROWS_PER_BLOCK;
    const float* xp = x   + (size_t)b0 * S_TOTAL + s;
    float*       op = out + (size_t)b0 * S_TOTAL + s;
    const float* cbase = &sc[t * 9];

    #pragma unroll 1
    for (int r = 0; r < ROWS_PER_BLOCK; r += 4) {
        float xv[4];
        #pragma unroll
        for (int k = 0; k < 4; k++)
            xv[k] = xp[(size_t)(r + k) * S_TOTAL];

        #pragma unroll
        for (int k = 0; k < 4; k++) {
            float tt = (xv[k] - g0) * invh;
            float fi = floorf(tt);
            fi = fminf(fmaxf(fi, 3.0f), 7.0f);     // valid intervals for x in [-1,1)
            float u  = tt - fi;
            int   i  = (int)fi;

            float u2 = u * u;
            float u3 = u2 * u;
            float om = 1.0f - u;
            float B0 = om * om * om * (1.0f / 6.0f);
            float B1 = fmaf(0.5f, u3, fmaf(-1.0f, u2, 2.0f / 3.0f));
            float B3 = u3 * (1.0f / 6.0f);
            float B2 = 1.0f - B0 - B1 - B3;         // partition of unity

            const float* c = cbase + (i - 3);
            float v = fmaf(B0, c[0], fmaf(B1, c[1], fmaf(B2, c[2], B3 * c[3])));
            op[(size_t)(r + k) * S_TOTAL] = v;
        }
    }
}

extern "C" void kernel_launch(void* const* d_in, const int* in_sizes, int n_in,
                              void* d_out, int out_size)
{
    const float* x     = (const float*)d_in[0];
    const float* coeff = (const float*)d_in[1];
    const float* grid  = (const float*)d_in[2];
    float*       out   = (float*)d_out;

    dim3 g(S_TOTAL / TILE_S, GRID_Y);   // (16, 64) = 1024 blocks
    bspline_kernel<<<g, THREADS>>>(x, coeff, grid, out);
}